// round 3
// baseline (speedup 1.0000x reference)
#include <cuda_runtime.h>
#include <math.h>

// Problem constants
#define NN 50000          // nodes
#define NE 500000         // original edges
#define ET (NE + NN)      // edges + self loops = 550000
#define H1N 4
#define D1 256            // H1*C1
#define C2 64
#define IND 128

// ---------------- device scratch (static, no allocation) ----------------
__device__ float    g_h1[NN * D1];        // layer1 projected features
__device__ float    g_out1[NN * D1];      // layer1 aggregated output (then elu'd in place)
__device__ float    g_h2[NN * C2];        // layer2 projected features
__device__ float    g_ssrc1[NN * H1N];
__device__ float    g_sdst1[NN * H1N];
__device__ unsigned g_m1[NN * H1N];
__device__ float    g_den1[NN * H1N];
__device__ float    g_alpha1[ET * H1N];
__device__ float    g_ssrc2[NN];
__device__ float    g_sdst2[NN];
__device__ unsigned g_m2[NN];
__device__ float    g_den2[NN];
__device__ float    g_alpha2[ET];
__device__ float    g_cnt[NN];
__device__ float    g_sum[NN];
__device__ float    g_loop[NN];
__device__ float    g_eproj[8];           // [0..3]=layer1 heads, [4]=layer2

// ordered-float <-> uint monotonic map for atomicMax on floats
__device__ __forceinline__ unsigned f2u(float f) {
    unsigned u = __float_as_uint(f);
    return (u & 0x80000000u) ? ~u : (u | 0x80000000u);
}
__device__ __forceinline__ float u2f(unsigned u) {
    return (u & 0x80000000u) ? __uint_as_float(u & 0x7FFFFFFFu) : __uint_as_float(~u);
}

// ---------------- kernels ----------------

__global__ void k_reset(float* __restrict__ dout, const float* __restrict__ b2) {
    int i = blockIdx.x * blockDim.x + threadIdx.x;
    if (i < NN * D1) g_out1[i] = 0.f;
    if (i < NN * C2) dout[i] = b2[i & 63];     // init output with bias2
    if (i < NN * H1N) { g_den1[i] = 0.f; g_m1[i] = 0u; }
    if (i < NN) { g_den2[i] = 0.f; g_m2[i] = 0u; g_cnt[i] = 0.f; g_sum[i] = 0.f; }
}

__global__ void k_loopstat(const int* __restrict__ dst, const float* __restrict__ ea) {
    int i = blockIdx.x * blockDim.x + threadIdx.x;
    if (i >= NE) return;
    int d = dst[i];
    atomicAdd(&g_cnt[d], 1.f);
    atomicAdd(&g_sum[d], ea[i]);
}

__global__ void k_loopattr() {
    int i = blockIdx.x * blockDim.x + threadIdx.x;
    if (i < NN) g_loop[i] = g_sum[i] / fmaxf(g_cnt[i], 1.f);
}

__global__ void k_eproj(const float* __restrict__ We1, const float* __restrict__ ae1,
                        const float* __restrict__ We2, const float* __restrict__ ae2) {
    __shared__ float sm[256];
    int t = threadIdx.x;
    sm[t] = We1[t] * ae1[t];
    __syncthreads();
    if (t < 4) {
        float s = 0.f;
        for (int j = 0; j < 64; j++) s += sm[t * 64 + j];
        g_eproj[t] = s;
    }
    __syncthreads();
    if (t < 64) sm[t] = We2[t] * ae2[t];
    __syncthreads();
    if (t == 0) {
        float s = 0.f;
        for (int j = 0; j < 64; j++) s += sm[j];
        g_eproj[4] = s;
    }
}

// GEMM1: h1 = x @ W1  (per block: 4 nodes x 256 cols; thread = 4 cols of one node)
__global__ void k_gemm1(const float* __restrict__ x, const float* __restrict__ W1,
                        const float* __restrict__ as1, const float* __restrict__ ad1) {
    __shared__ float xs[4 * IND];
    int tid = threadIdx.x;
    int g = tid >> 6;          // node within block (0..3)
    int lane = tid & 63;       // float4 column (0..63)
    int nodeBase = blockIdx.x * 4;
    for (int i = tid; i < 4 * IND; i += 256) xs[i] = x[nodeBase * IND + i];
    __syncthreads();

    const float4* __restrict__ W4 = (const float4*)W1;
    const float* xr = xs + g * IND;
    float4 acc = make_float4(0.f, 0.f, 0.f, 0.f);
#pragma unroll 8
    for (int k = 0; k < IND; k++) {
        float xv = xr[k];
        float4 w = W4[k * 64 + lane];
        acc.x += xv * w.x; acc.y += xv * w.y; acc.z += xv * w.z; acc.w += xv * w.w;
    }
    int node = nodeBase + g;
    ((float4*)g_h1)[node * 64 + lane] = acc;

    float4 av = ((const float4*)as1)[lane];
    float4 dv = ((const float4*)ad1)[lane];
    float ps = acc.x * av.x + acc.y * av.y + acc.z * av.z + acc.w * av.w;
    float pd = acc.x * dv.x + acc.y * dv.y + acc.z * dv.z + acc.w * dv.w;
#pragma unroll
    for (int off = 8; off; off >>= 1) {
        ps += __shfl_xor_sync(0xffffffffu, ps, off);
        pd += __shfl_xor_sync(0xffffffffu, pd, off);
    }
    if ((lane & 15) == 0) {
        int h = lane >> 4;
        g_ssrc1[node * 4 + h] = ps;
        g_sdst1[node * 4 + h] = pd;
    }
}

__global__ void k_alpha1(const int* __restrict__ src, const int* __restrict__ dst,
                         const float* __restrict__ ea) {
    int e = blockIdx.x * blockDim.x + threadIdx.x;
    if (e >= ET) return;
    int s, d; float a;
    if (e < NE) { s = src[e]; d = dst[e]; a = ea[e]; }
    else { s = e - NE; d = s; a = g_loop[s]; }
    float4 ss = ((const float4*)g_ssrc1)[s];
    float4 sd = ((const float4*)g_sdst1)[d];
    float4 al;
    al.x = ss.x + sd.x + a * g_eproj[0];
    al.y = ss.y + sd.y + a * g_eproj[1];
    al.z = ss.z + sd.z + a * g_eproj[2];
    al.w = ss.w + sd.w + a * g_eproj[3];
    al.x = al.x > 0.f ? al.x : 0.2f * al.x;
    al.y = al.y > 0.f ? al.y : 0.2f * al.y;
    al.z = al.z > 0.f ? al.z : 0.2f * al.z;
    al.w = al.w > 0.f ? al.w : 0.2f * al.w;
    ((float4*)g_alpha1)[e] = al;
    int b = d * 4;
    atomicMax(&g_m1[b + 0], f2u(al.x));
    atomicMax(&g_m1[b + 1], f2u(al.y));
    atomicMax(&g_m1[b + 2], f2u(al.z));
    atomicMax(&g_m1[b + 3], f2u(al.w));
}

__global__ void k_exp1(const int* __restrict__ dst) {
    int e = blockIdx.x * blockDim.x + threadIdx.x;
    if (e >= ET) return;
    int d = (e < NE) ? dst[e] : (e - NE);
    float4 al = ((const float4*)g_alpha1)[e];
    uint4 mu = ((const uint4*)g_m1)[d];
    al.x = __expf(al.x - u2f(mu.x));
    al.y = __expf(al.y - u2f(mu.y));
    al.z = __expf(al.z - u2f(mu.z));
    al.w = __expf(al.w - u2f(mu.w));
    int b = d * 4;
    atomicAdd(&g_den1[b + 0], al.x);
    atomicAdd(&g_den1[b + 1], al.y);
    atomicAdd(&g_den1[b + 2], al.z);
    atomicAdd(&g_den1[b + 3], al.w);
    ((float4*)g_alpha1)[e] = al;
}

// scatter1: out1[dst] += h1[src] * alpha/denom  -- 64 threads per edge (float4 each)
__global__ void k_scatter1(const int* __restrict__ src, const int* __restrict__ dst) {
    int tid = threadIdx.x;
    int e = blockIdx.x * 4 + (tid >> 6);
    int lane = tid & 63;
    int s, d;
    if (e < NE) { s = src[e]; d = dst[e]; }
    else { s = e - NE; d = s; }
    int h = lane >> 4;
    float w = g_alpha1[e * 4 + h] / (g_den1[d * 4 + h] + 1e-16f);
    float4 v = ((const float4*)g_h1)[s * 64 + lane];
    float* o = g_out1 + d * D1 + lane * 4;
    atomicAdd(o + 0, v.x * w);
    atomicAdd(o + 1, v.y * w);
    atomicAdd(o + 2, v.z * w);
    atomicAdd(o + 3, v.w * w);
}

__global__ void k_elubias(const float* __restrict__ b1) {
    int i = blockIdx.x * blockDim.x + threadIdx.x;
    if (i >= NN * D1) return;
    float v = g_out1[i] + b1[i & 255];
    g_out1[i] = v > 0.f ? v : (__expf(v) - 1.f);
}

// GEMM2: h2 = elu_out @ W2  (per block: 16 nodes x 64 cols; thread = 4 cols of one node)
__global__ void k_gemm2(const float* __restrict__ W2,
                        const float* __restrict__ as2, const float* __restrict__ ad2) {
    __shared__ float xs[16 * D1];
    int tid = threadIdx.x;
    int g = tid >> 4;          // node within block (0..15)
    int q = tid & 15;          // float4 column (0..15)
    int nodeBase = blockIdx.x * 16;
    const float4* src4 = (const float4*)(g_out1 + nodeBase * D1);
    float4* xs4 = (float4*)xs;
    for (int i = tid; i < 16 * D1 / 4; i += 256) xs4[i] = src4[i];
    __syncthreads();

    const float4* __restrict__ W4 = (const float4*)W2;
    const float* xr = xs + g * D1;
    float4 acc = make_float4(0.f, 0.f, 0.f, 0.f);
#pragma unroll 8
    for (int k = 0; k < D1; k++) {
        float xv = xr[k];
        float4 w = W4[k * 16 + q];
        acc.x += xv * w.x; acc.y += xv * w.y; acc.z += xv * w.z; acc.w += xv * w.w;
    }
    int node = nodeBase + g;
    ((float4*)g_h2)[node * 16 + q] = acc;

    float4 av = ((const float4*)as2)[q];
    float4 dv = ((const float4*)ad2)[q];
    float ps = acc.x * av.x + acc.y * av.y + acc.z * av.z + acc.w * av.w;
    float pd = acc.x * dv.x + acc.y * dv.y + acc.z * dv.z + acc.w * dv.w;
#pragma unroll
    for (int off = 8; off; off >>= 1) {
        ps += __shfl_xor_sync(0xffffffffu, ps, off);
        pd += __shfl_xor_sync(0xffffffffu, pd, off);
    }
    if (q == 0) { g_ssrc2[node] = ps; g_sdst2[node] = pd; }
}

__global__ void k_alpha2(const int* __restrict__ src, const int* __restrict__ dst,
                         const float* __restrict__ ea) {
    int e = blockIdx.x * blockDim.x + threadIdx.x;
    if (e >= ET) return;
    int s, d; float a;
    if (e < NE) { s = src[e]; d = dst[e]; a = ea[e]; }
    else { s = e - NE; d = s; a = g_loop[s]; }
    float al = g_ssrc2[s] + g_sdst2[d] + a * g_eproj[4];
    al = al > 0.f ? al : 0.2f * al;
    g_alpha2[e] = al;
    atomicMax(&g_m2[d], f2u(al));
}

__global__ void k_exp2(const int* __restrict__ dst) {
    int e = blockIdx.x * blockDim.x + threadIdx.x;
    if (e >= ET) return;
    int d = (e < NE) ? dst[e] : (e - NE);
    float v = __expf(g_alpha2[e] - u2f(g_m2[d]));
    atomicAdd(&g_den2[d], v);
    g_alpha2[e] = v;
}

// scatter2: out[dst] += h2[src] * alpha/denom  -- 16 threads per edge (float4 each)
__global__ void k_scatter2(const int* __restrict__ src, const int* __restrict__ dst,
                           float* __restrict__ dout) {
    int tid = threadIdx.x;
    int e = blockIdx.x * 16 + (tid >> 4);
    int q = tid & 15;
    int s, d;
    if (e < NE) { s = src[e]; d = dst[e]; }
    else { s = e - NE; d = s; }
    float w = g_alpha2[e] / (g_den2[d] + 1e-16f);
    float4 v = ((const float4*)g_h2)[s * 16 + q];
    float* o = dout + d * C2 + q * 4;
    atomicAdd(o + 0, v.x * w);
    atomicAdd(o + 1, v.y * w);
    atomicAdd(o + 2, v.z * w);
    atomicAdd(o + 3, v.w * w);
}

// ---------------- launch ----------------
extern "C" void kernel_launch(void* const* d_in, const int* in_sizes, int n_in,
                              void* d_out, int out_size) {
    const float* x   = (const float*)d_in[0];
    const int*   ei  = (const int*)d_in[1];
    const float* ea  = (const float*)d_in[2];
    const float* W1  = (const float*)d_in[3];
    const float* We1 = (const float*)d_in[4];
    const float* as1 = (const float*)d_in[5];
    const float* ad1 = (const float*)d_in[6];
    const float* ae1 = (const float*)d_in[7];
    const float* b1  = (const float*)d_in[8];
    const float* W2  = (const float*)d_in[9];
    const float* We2 = (const float*)d_in[10];
    const float* as2 = (const float*)d_in[11];
    const float* ad2 = (const float*)d_in[12];
    const float* ae2 = (const float*)d_in[13];
    const float* b2  = (const float*)d_in[14];
    float* dout = (float*)d_out;

    const int* src = ei;
    const int* dst = ei + NE;

    k_reset<<<(NN * D1) / 256, 256>>>(dout, b2);
    k_loopstat<<<(NE + 255) / 256, 256>>>(dst, ea);
    k_loopattr<<<(NN + 255) / 256, 256>>>();
    k_eproj<<<1, 256>>>(We1, ae1, We2, ae2);

    k_gemm1<<<NN / 4, 256>>>(x, W1, as1, ad1);
    k_alpha1<<<(ET + 255) / 256, 256>>>(src, dst, ea);
    k_exp1<<<(ET + 255) / 256, 256>>>(dst);
    k_scatter1<<<ET / 4, 256>>>(src, dst);
    k_elubias<<<(NN * D1) / 256, 256>>>(b1);

    k_gemm2<<<NN / 16, 256>>>(W2, as2, ad2);
    k_alpha2<<<(ET + 255) / 256, 256>>>(src, dst, ea);
    k_exp2<<<(ET + 255) / 256, 256>>>(dst);
    k_scatter2<<<ET / 16, 256>>>(src, dst, dout);
}

// round 4
// speedup vs baseline: 2.0132x; 2.0132x over previous
#include <cuda_runtime.h>
#include <math.h>

// Problem constants
#define NN 50000          // nodes
#define NE 500000         // original edges
#define ET (NE + NN)      // edges + self loops = 550000
#define D1 256            // layer1 out (4 heads x 64)
#define C2 64
#define IND 128

// ---------------- device scratch (static, no allocation) ----------------
__device__ float  g_h1[NN * D1];        // layer1 projected features
__device__ float  g_out1[NN * D1];      // layer1 aggregated+elu output
__device__ float  g_h2[NN * C2];        // layer2 projected features
__device__ float  g_ssrc1[NN * 4];
__device__ float  g_sdst1[NN * 4];
__device__ float  g_ssrc2[NN];
__device__ float  g_sdst2[NN];
__device__ float4 g_alpha1[ET];
__device__ float  g_alpha2[ET];
__device__ float  g_loop[NN];
__device__ __align__(16) float g_eproj[8];   // [0..3]=layer1 heads, [4]=layer2
// CSR
__device__ int    g_deg[NN];
__device__ int    g_off[NN + 1];
__device__ int    g_cur[NN];
__device__ int    g_eid[ET];
__device__ int    g_srcs[ET];

// ---------------- CSR build ----------------

__global__ void k_zero() {
    int i = blockIdx.x * blockDim.x + threadIdx.x;
    if (i < NN) g_deg[i] = 1;                 // self loop
}

__global__ void k_hist(const int* __restrict__ dst) {
    int e = blockIdx.x * blockDim.x + threadIdx.x;
    if (e < NE) atomicAdd(&g_deg[dst[e]], 1);
}

// single block 1024 threads, exclusive scan of g_deg -> g_off, copy to g_cur
__global__ void k_scan() {
    __shared__ int part[1024];
    int t = threadIdx.x;
    const int CH = 49;                        // 1024*49 = 50176 >= NN
    int base = t * CH;
    int s = 0;
    for (int i = 0; i < CH; i++) {
        int idx = base + i;
        if (idx < NN) s += g_deg[idx];
    }
    part[t] = s;
    __syncthreads();
    for (int off = 1; off < 1024; off <<= 1) {
        int v = (t >= off) ? part[t - off] : 0;
        __syncthreads();
        part[t] += v;
        __syncthreads();
    }
    int run = part[t] - s;                    // exclusive prefix
    for (int i = 0; i < CH; i++) {
        int idx = base + i;
        if (idx < NN) { g_off[idx] = run; g_cur[idx] = run; run += g_deg[idx]; }
    }
    if (t == 1023) g_off[NN] = part[1023];
}

__global__ void k_fill(const int* __restrict__ src, const int* __restrict__ dst) {
    int e = blockIdx.x * blockDim.x + threadIdx.x;
    if (e >= ET) return;
    int s, d;
    if (e < NE) { s = src[e]; d = dst[e]; }
    else { s = e - NE; d = s; }
    int pos = atomicAdd(&g_cur[d], 1);
    g_eid[pos] = e;
    g_srcs[pos] = s;
}

// warp per node: loop edge attr = mean of incoming original-edge attrs
__global__ void k_loopw(const float* __restrict__ ea) {
    int n = (blockIdx.x * blockDim.x + threadIdx.x) >> 5;
    int lane = threadIdx.x & 31;
    if (n >= NN) return;
    int o0 = g_off[n], deg = g_off[n + 1] - o0;
    float sum = 0.f;
    for (int i = lane; i < deg; i += 32) {
        int e = g_eid[o0 + i];
        if (e < NE) sum += ea[e];
    }
#pragma unroll
    for (int off = 16; off; off >>= 1) sum += __shfl_xor_sync(0xffffffffu, sum, off);
    if (lane == 0) g_loop[n] = sum / fmaxf((float)(deg - 1), 1.f);
}

__global__ void k_eproj(const float* __restrict__ We1, const float* __restrict__ ae1,
                        const float* __restrict__ We2, const float* __restrict__ ae2) {
    __shared__ float sm[256];
    int t = threadIdx.x;
    sm[t] = We1[t] * ae1[t];
    __syncthreads();
    if (t < 4) {
        float s = 0.f;
        for (int j = 0; j < 64; j++) s += sm[t * 64 + j];
        g_eproj[t] = s;
    }
    __syncthreads();
    if (t < 64) sm[t] = We2[t] * ae2[t];
    __syncthreads();
    if (t == 0) {
        float s = 0.f;
        for (int j = 0; j < 64; j++) s += sm[j];
        g_eproj[4] = s;
    }
}

// ---------------- GEMMs ----------------

// GEMM1: h1 = x @ W1. Block: 32 nodes x 256 cols; thread: 8 nodes x 4 cols.
__global__ void __launch_bounds__(256) k_gemm1(const float* __restrict__ x,
                                               const float* __restrict__ W1) {
    __shared__ float xs[32 * IND];            // 16KB
    int t = threadIdx.x;
    int tx = t & 63, ty = t >> 6;             // tx: float4 col, ty: node group
    int nodeBase = blockIdx.x * 32;
    const float4* xg = (const float4*)x;
    float4* xs4 = (float4*)xs;
#pragma unroll
    for (int i = 0; i < 4; i++) {
        int idx = nodeBase * 32 + t + i * 256;        // global float4 index (NN*32 total)
        xs4[t + i * 256] = (idx < NN * 32) ? xg[idx] : make_float4(0.f, 0.f, 0.f, 0.f);
    }
    __syncthreads();
    float4 acc[8];
#pragma unroll
    for (int i = 0; i < 8; i++) acc[i] = make_float4(0.f, 0.f, 0.f, 0.f);
    const float4* __restrict__ W4 = (const float4*)W1;
#pragma unroll 4
    for (int k = 0; k < IND; k++) {
        float4 w = W4[k * 64 + tx];
#pragma unroll
        for (int i = 0; i < 8; i++) {
            float xv = xs[(ty * 8 + i) * IND + k];
            acc[i].x += xv * w.x; acc[i].y += xv * w.y;
            acc[i].z += xv * w.z; acc[i].w += xv * w.w;
        }
    }
#pragma unroll
    for (int i = 0; i < 8; i++) {
        int node = nodeBase + ty * 8 + i;
        if (node < NN) ((float4*)g_h1)[node * 64 + tx] = acc[i];
    }
}

// GEMM2: h2 = out1 @ W2. Block: 32 nodes x 64 cols; thread: 2 nodes x 4 cols.
__global__ void __launch_bounds__(256) k_gemm2(const float* __restrict__ W2) {
    __shared__ float xs[32 * D1];             // 32KB
    int t = threadIdx.x;
    int tx = t & 15, ty = t >> 4;             // tx: float4 col (0..15), ty: 0..15
    int nodeBase = blockIdx.x * 32;
    const float4* xg = (const float4*)g_out1;
    float4* xs4 = (float4*)xs;
#pragma unroll
    for (int i = 0; i < 8; i++) {
        int idx = nodeBase * 64 + t + i * 256;        // global float4 index (NN*64 total)
        xs4[t + i * 256] = (idx < NN * 64) ? xg[idx] : make_float4(0.f, 0.f, 0.f, 0.f);
    }
    __syncthreads();
    float4 acc[2];
    acc[0] = make_float4(0.f, 0.f, 0.f, 0.f);
    acc[1] = make_float4(0.f, 0.f, 0.f, 0.f);
    const float4* __restrict__ W4 = (const float4*)W2;
#pragma unroll 4
    for (int k = 0; k < D1; k++) {
        float4 w = W4[k * 16 + tx];
#pragma unroll
        for (int i = 0; i < 2; i++) {
            float xv = xs[(ty * 2 + i) * D1 + k];
            acc[i].x += xv * w.x; acc[i].y += xv * w.y;
            acc[i].z += xv * w.z; acc[i].w += xv * w.w;
        }
    }
#pragma unroll
    for (int i = 0; i < 2; i++) {
        int node = nodeBase + ty * 2 + i;
        if (node < NN) ((float4*)g_h2)[node * 16 + tx] = acc[i];
    }
}

// ---------------- attention score dots ----------------

// warp per node: ssrc1/sdst1 per head
__global__ void k_score1(const float* __restrict__ as1, const float* __restrict__ ad1) {
    int n = (blockIdx.x * blockDim.x + threadIdx.x) >> 5;
    int lane = threadIdx.x & 31;
    if (n >= NN) return;
    const float4* row = (const float4*)g_h1 + n * 64;
    float4 v0 = row[lane * 2], v1 = row[lane * 2 + 1];
    float4 a0 = ((const float4*)as1)[lane * 2], a1 = ((const float4*)as1)[lane * 2 + 1];
    float4 d0 = ((const float4*)ad1)[lane * 2], d1 = ((const float4*)ad1)[lane * 2 + 1];
    float ps = v0.x * a0.x + v0.y * a0.y + v0.z * a0.z + v0.w * a0.w
             + v1.x * a1.x + v1.y * a1.y + v1.z * a1.z + v1.w * a1.w;
    float pd = v0.x * d0.x + v0.y * d0.y + v0.z * d0.z + v0.w * d0.w
             + v1.x * d1.x + v1.y * d1.y + v1.z * d1.z + v1.w * d1.w;
#pragma unroll
    for (int off = 4; off; off >>= 1) {
        ps += __shfl_xor_sync(0xffffffffu, ps, off);
        pd += __shfl_xor_sync(0xffffffffu, pd, off);
    }
    if ((lane & 7) == 0) {
        int h = lane >> 3;
        g_ssrc1[n * 4 + h] = ps;
        g_sdst1[n * 4 + h] = pd;
    }
}

// warp per node: ssrc2/sdst2 (single head)
__global__ void k_score2(const float* __restrict__ as2, const float* __restrict__ ad2) {
    int n = (blockIdx.x * blockDim.x + threadIdx.x) >> 5;
    int lane = threadIdx.x & 31;
    if (n >= NN) return;
    float2 v = ((const float2*)(g_h2 + n * 64))[lane];
    float2 a = ((const float2*)as2)[lane];
    float2 d = ((const float2*)ad2)[lane];
    float ps = v.x * a.x + v.y * a.y;
    float pd = v.x * d.x + v.y * d.y;
#pragma unroll
    for (int off = 16; off; off >>= 1) {
        ps += __shfl_xor_sync(0xffffffffu, ps, off);
        pd += __shfl_xor_sync(0xffffffffu, pd, off);
    }
    if (lane == 0) { g_ssrc2[n] = ps; g_sdst2[n] = pd; }
}

// ---------------- fused softmax + aggregation ----------------

// warp per dst node, layer1 (4 heads, 256 feature cols)
__global__ void __launch_bounds__(256) k_agg1(const float* __restrict__ ea,
                                              const float* __restrict__ b1) {
    int n = (blockIdx.x * blockDim.x + threadIdx.x) >> 5;
    int lane = threadIdx.x & 31;
    if (n >= NN) return;
    int o0 = g_off[n], deg = g_off[n + 1] - o0;
    float4 ep = *((const float4*)g_eproj);
    float4 sd = ((const float4*)g_sdst1)[n];

    // pass A: alpha (leaky relu), per-head max
    float4 mx = make_float4(-1e30f, -1e30f, -1e30f, -1e30f);
    for (int i = lane; i < deg; i += 32) {
        int p = o0 + i;
        int e = g_eid[p];
        int s = g_srcs[p];
        float a = (e < NE) ? ea[e] : g_loop[n];
        float4 ss = ((const float4*)g_ssrc1)[s];
        float4 al;
        al.x = ss.x + sd.x + a * ep.x;
        al.y = ss.y + sd.y + a * ep.y;
        al.z = ss.z + sd.z + a * ep.z;
        al.w = ss.w + sd.w + a * ep.w;
        al.x = al.x > 0.f ? al.x : 0.2f * al.x;
        al.y = al.y > 0.f ? al.y : 0.2f * al.y;
        al.z = al.z > 0.f ? al.z : 0.2f * al.z;
        al.w = al.w > 0.f ? al.w : 0.2f * al.w;
        g_alpha1[p] = al;
        mx.x = fmaxf(mx.x, al.x); mx.y = fmaxf(mx.y, al.y);
        mx.z = fmaxf(mx.z, al.z); mx.w = fmaxf(mx.w, al.w);
    }
#pragma unroll
    for (int off = 16; off; off >>= 1) {
        mx.x = fmaxf(mx.x, __shfl_xor_sync(0xffffffffu, mx.x, off));
        mx.y = fmaxf(mx.y, __shfl_xor_sync(0xffffffffu, mx.y, off));
        mx.z = fmaxf(mx.z, __shfl_xor_sync(0xffffffffu, mx.z, off));
        mx.w = fmaxf(mx.w, __shfl_xor_sync(0xffffffffu, mx.w, off));
    }
    __syncwarp();

    // pass B: exp + sum
    float4 se = make_float4(0.f, 0.f, 0.f, 0.f);
    for (int i = lane; i < deg; i += 32) {
        int p = o0 + i;
        float4 al = g_alpha1[p];
        al.x = __expf(al.x - mx.x); al.y = __expf(al.y - mx.y);
        al.z = __expf(al.z - mx.z); al.w = __expf(al.w - mx.w);
        g_alpha1[p] = al;
        se.x += al.x; se.y += al.y; se.z += al.z; se.w += al.w;
    }
#pragma unroll
    for (int off = 16; off; off >>= 1) {
        se.x += __shfl_xor_sync(0xffffffffu, se.x, off);
        se.y += __shfl_xor_sync(0xffffffffu, se.y, off);
        se.z += __shfl_xor_sync(0xffffffffu, se.z, off);
        se.w += __shfl_xor_sync(0xffffffffu, se.w, off);
    }
    float4 wv;
    wv.x = 1.f / (se.x + 1e-16f); wv.y = 1.f / (se.y + 1e-16f);
    wv.z = 1.f / (se.z + 1e-16f); wv.w = 1.f / (se.w + 1e-16f);
    __syncwarp();

    // pass C: coalesced feature gather-accumulate; lane covers cols [lane*8, lane*8+8)
    int h = lane >> 3;
    float wsel = (h == 0) ? wv.x : (h == 1) ? wv.y : (h == 2) ? wv.z : wv.w;
    float4 acc0 = make_float4(0.f, 0.f, 0.f, 0.f);
    float4 acc1 = make_float4(0.f, 0.f, 0.f, 0.f);
    for (int i = 0; i < deg; i++) {
        int p = o0 + i;
        float4 al = g_alpha1[p];
        float aw = ((h == 0) ? al.x : (h == 1) ? al.y : (h == 2) ? al.z : al.w) * wsel;
        int s = g_srcs[p];
        const float4* row = (const float4*)g_h1 + s * 64;
        float4 v0 = row[lane * 2], v1 = row[lane * 2 + 1];
        acc0.x += aw * v0.x; acc0.y += aw * v0.y; acc0.z += aw * v0.z; acc0.w += aw * v0.w;
        acc1.x += aw * v1.x; acc1.y += aw * v1.y; acc1.z += aw * v1.z; acc1.w += aw * v1.w;
    }
    float4 bb0 = ((const float4*)b1)[lane * 2], bb1 = ((const float4*)b1)[lane * 2 + 1];
    acc0.x += bb0.x; acc0.y += bb0.y; acc0.z += bb0.z; acc0.w += bb0.w;
    acc1.x += bb1.x; acc1.y += bb1.y; acc1.z += bb1.z; acc1.w += bb1.w;
    acc0.x = acc0.x > 0.f ? acc0.x : (__expf(acc0.x) - 1.f);
    acc0.y = acc0.y > 0.f ? acc0.y : (__expf(acc0.y) - 1.f);
    acc0.z = acc0.z > 0.f ? acc0.z : (__expf(acc0.z) - 1.f);
    acc0.w = acc0.w > 0.f ? acc0.w : (__expf(acc0.w) - 1.f);
    acc1.x = acc1.x > 0.f ? acc1.x : (__expf(acc1.x) - 1.f);
    acc1.y = acc1.y > 0.f ? acc1.y : (__expf(acc1.y) - 1.f);
    acc1.z = acc1.z > 0.f ? acc1.z : (__expf(acc1.z) - 1.f);
    acc1.w = acc1.w > 0.f ? acc1.w : (__expf(acc1.w) - 1.f);
    float4* orow = (float4*)g_out1 + n * 64;
    orow[lane * 2] = acc0;
    orow[lane * 2 + 1] = acc1;
}

// warp per dst node, layer2 (1 head, 64 cols) -> final output + bias2
__global__ void __launch_bounds__(256) k_agg2(const float* __restrict__ ea,
                                              const float* __restrict__ b2,
                                              float* __restrict__ dout) {
    int n = (blockIdx.x * blockDim.x + threadIdx.x) >> 5;
    int lane = threadIdx.x & 31;
    if (n >= NN) return;
    int o0 = g_off[n], deg = g_off[n + 1] - o0;
    float ep = g_eproj[4];
    float sdn = g_sdst2[n];

    float mx = -1e30f;
    for (int i = lane; i < deg; i += 32) {
        int p = o0 + i;
        int e = g_eid[p];
        int s = g_srcs[p];
        float a = (e < NE) ? ea[e] : g_loop[n];
        float al = g_ssrc2[s] + sdn + a * ep;
        al = al > 0.f ? al : 0.2f * al;
        g_alpha2[p] = al;
        mx = fmaxf(mx, al);
    }
#pragma unroll
    for (int off = 16; off; off >>= 1) mx = fmaxf(mx, __shfl_xor_sync(0xffffffffu, mx, off));
    __syncwarp();

    float se = 0.f;
    for (int i = lane; i < deg; i += 32) {
        int p = o0 + i;
        float v = __expf(g_alpha2[p] - mx);
        g_alpha2[p] = v;
        se += v;
    }
#pragma unroll
    for (int off = 16; off; off >>= 1) se += __shfl_xor_sync(0xffffffffu, se, off);
    float w = 1.f / (se + 1e-16f);
    __syncwarp();

    float2 acc = make_float2(0.f, 0.f);
    for (int i = 0; i < deg; i++) {
        int p = o0 + i;
        float aw = g_alpha2[p] * w;
        int s = g_srcs[p];
        float2 v = ((const float2*)(g_h2 + s * 64))[lane];
        acc.x += aw * v.x;
        acc.y += aw * v.y;
    }
    float2 bb = ((const float2*)b2)[lane];
    ((float2*)(dout + n * 64))[lane] = make_float2(acc.x + bb.x, acc.y + bb.y);
}

// ---------------- launch ----------------
extern "C" void kernel_launch(void* const* d_in, const int* in_sizes, int n_in,
                              void* d_out, int out_size) {
    const float* x   = (const float*)d_in[0];
    const int*   ei  = (const int*)d_in[1];
    const float* ea  = (const float*)d_in[2];
    const float* W1  = (const float*)d_in[3];
    const float* We1 = (const float*)d_in[4];
    const float* as1 = (const float*)d_in[5];
    const float* ad1 = (const float*)d_in[6];
    const float* ae1 = (const float*)d_in[7];
    const float* b1  = (const float*)d_in[8];
    const float* W2  = (const float*)d_in[9];
    const float* We2 = (const float*)d_in[10];
    const float* as2 = (const float*)d_in[11];
    const float* ad2 = (const float*)d_in[12];
    const float* ae2 = (const float*)d_in[13];
    const float* b2  = (const float*)d_in[14];
    float* dout = (float*)d_out;

    const int* src = ei;
    const int* dst = ei + NE;

    const int WPB = 8;                         // warps (nodes) per 256-thread block
    const int NB  = (NN + WPB - 1) / WPB;      // 6250

    k_zero<<<(NN + 255) / 256, 256>>>();
    k_hist<<<(NE + 255) / 256, 256>>>(dst);
    k_scan<<<1, 1024>>>();
    k_fill<<<(ET + 255) / 256, 256>>>(src, dst);
    k_loopw<<<NB, 256>>>(ea);
    k_eproj<<<1, 256>>>(We1, ae1, We2, ae2);

    k_gemm1<<<(NN + 31) / 32, 256>>>(x, W1);
    k_score1<<<NB, 256>>>(as1, ad1);
    k_agg1<<<NB, 256>>>(ea, b1);

    k_gemm2<<<(NN + 31) / 32, 256>>>(W2);
    k_score2<<<NB, 256>>>(as2, ad2);
    k_agg2<<<NB, 256>>>(ea, b2, dout);
}

// round 5
// speedup vs baseline: 2.0202x; 1.0035x over previous
#include <cuda_runtime.h>
#include <math.h>

// Problem constants
#define NN 50000          // nodes
#define NE 500000         // original edges
#define ET (NE + NN)      // edges + self loops = 550000
#define D1 256            // layer1 out (4 heads x 64)
#define C2 64
#define IND 128

// ---------------- device scratch (static, no allocation) ----------------
__device__ float  g_h1[NN * D1];        // layer1 projected features
__device__ float  g_out1[NN * D1];      // layer1 aggregated+elu output
__device__ float  g_h2[NN * C2];        // layer2 projected features
__device__ float  g_ssrc1[NN * 4];
__device__ float  g_sdst1[NN * 4];
__device__ float  g_ssrc2[NN];
__device__ float  g_sdst2[NN];
__device__ float4 g_alpha1[ET];
__device__ float  g_alpha2[ET];
__device__ float  g_loop[NN];
__device__ __align__(16) float g_eproj[8];   // [0..3]=layer1 heads, [4]=layer2
// CSR
__device__ int    g_deg[NN];
__device__ int    g_off[NN + 1];
__device__ int    g_cur[NN];
__device__ int    g_eid[ET];
__device__ int    g_srcs[ET];

// ---------------- CSR build ----------------

__global__ void k_zero() {
    int i = blockIdx.x * blockDim.x + threadIdx.x;
    if (i < NN) g_deg[i] = 1;                 // self loop
}

__global__ void k_hist(const int* __restrict__ dst) {
    int e = blockIdx.x * blockDim.x + threadIdx.x;
    if (e < NE) atomicAdd(&g_deg[dst[e]], 1);
}

// single block 1024 threads, exclusive scan of g_deg -> g_off, copy to g_cur
__global__ void k_scan() {
    __shared__ int part[1024];
    int t = threadIdx.x;
    const int CH = 49;                        // 1024*49 = 50176 >= NN
    int base = t * CH;
    int s = 0;
    for (int i = 0; i < CH; i++) {
        int idx = base + i;
        if (idx < NN) s += g_deg[idx];
    }
    part[t] = s;
    __syncthreads();
    for (int off = 1; off < 1024; off <<= 1) {
        int v = (t >= off) ? part[t - off] : 0;
        __syncthreads();
        part[t] += v;
        __syncthreads();
    }
    int run = part[t] - s;                    // exclusive prefix
    for (int i = 0; i < CH; i++) {
        int idx = base + i;
        if (idx < NN) { g_off[idx] = run; g_cur[idx] = run; run += g_deg[idx]; }
    }
    if (t == 1023) g_off[NN] = part[1023];
}

__global__ void k_fill(const int* __restrict__ src, const int* __restrict__ dst) {
    int e = blockIdx.x * blockDim.x + threadIdx.x;
    if (e >= ET) return;
    int s, d;
    if (e < NE) { s = src[e]; d = dst[e]; }
    else { s = e - NE; d = s; }
    int pos = atomicAdd(&g_cur[d], 1);
    g_eid[pos] = e;
    g_srcs[pos] = s;
}

// warp per node: loop edge attr = mean of incoming original-edge attrs
__global__ void k_loopw(const float* __restrict__ ea) {
    int n = (blockIdx.x * blockDim.x + threadIdx.x) >> 5;
    int lane = threadIdx.x & 31;
    if (n >= NN) return;
    int o0 = g_off[n], deg = g_off[n + 1] - o0;
    float sum = 0.f;
    for (int i = lane; i < deg; i += 32) {
        int e = g_eid[o0 + i];
        if (e < NE) sum += ea[e];
    }
#pragma unroll
    for (int off = 16; off; off >>= 1) sum += __shfl_xor_sync(0xffffffffu, sum, off);
    if (lane == 0) g_loop[n] = sum / fmaxf((float)(deg - 1), 1.f);
}

__global__ void k_eproj(const float* __restrict__ We1, const float* __restrict__ ae1,
                        const float* __restrict__ We2, const float* __restrict__ ae2) {
    __shared__ float sm[256];
    int t = threadIdx.x;
    sm[t] = We1[t] * ae1[t];
    __syncthreads();
    if (t < 4) {
        float s = 0.f;
        for (int j = 0; j < 64; j++) s += sm[t * 64 + j];
        g_eproj[t] = s;
    }
    __syncthreads();
    if (t < 64) sm[t] = We2[t] * ae2[t];
    __syncthreads();
    if (t == 0) {
        float s = 0.f;
        for (int j = 0; j < 64; j++) s += sm[j];
        g_eproj[4] = s;
    }
}

// ---------------- GEMMs ----------------

// GEMM1: h1 = x @ W1. Block: 32 nodes x 256 cols; thread: 8 nodes x 4 cols.
__global__ void __launch_bounds__(256) k_gemm1(const float* __restrict__ x,
                                               const float* __restrict__ W1) {
    __shared__ float xs[32 * IND];            // 16KB
    int t = threadIdx.x;
    int tx = t & 63, ty = t >> 6;             // tx: float4 col, ty: node group
    int nodeBase = blockIdx.x * 32;
    const float4* xg = (const float4*)x;
    float4* xs4 = (float4*)xs;
#pragma unroll
    for (int i = 0; i < 4; i++) {
        int idx = nodeBase * 32 + t + i * 256;        // global float4 index (NN*32 total)
        xs4[t + i * 256] = (idx < NN * 32) ? xg[idx] : make_float4(0.f, 0.f, 0.f, 0.f);
    }
    __syncthreads();
    float4 acc[8];
#pragma unroll
    for (int i = 0; i < 8; i++) acc[i] = make_float4(0.f, 0.f, 0.f, 0.f);
    const float4* __restrict__ W4 = (const float4*)W1;
#pragma unroll 4
    for (int k = 0; k < IND; k++) {
        float4 w = W4[k * 64 + tx];
#pragma unroll
        for (int i = 0; i < 8; i++) {
            float xv = xs[(ty * 8 + i) * IND + k];
            acc[i].x += xv * w.x; acc[i].y += xv * w.y;
            acc[i].z += xv * w.z; acc[i].w += xv * w.w;
        }
    }
#pragma unroll
    for (int i = 0; i < 8; i++) {
        int node = nodeBase + ty * 8 + i;
        if (node < NN) ((float4*)g_h1)[node * 64 + tx] = acc[i];
    }
}

// GEMM2: h2 = out1 @ W2. Block: 32 nodes x 64 cols; thread: 2 nodes x 4 cols.
__global__ void __launch_bounds__(256) k_gemm2(const float* __restrict__ W2) {
    __shared__ float xs[32 * D1];             // 32KB
    int t = threadIdx.x;
    int tx = t & 15, ty = t >> 4;             // tx: float4 col (0..15), ty: 0..15
    int nodeBase = blockIdx.x * 32;
    const float4* xg = (const float4*)g_out1;
    float4* xs4 = (float4*)xs;
#pragma unroll
    for (int i = 0; i < 8; i++) {
        int idx = nodeBase * 64 + t + i * 256;        // global float4 index (NN*64 total)
        xs4[t + i * 256] = (idx < NN * 64) ? xg[idx] : make_float4(0.f, 0.f, 0.f, 0.f);
    }
    __syncthreads();
    float4 acc[2];
    acc[0] = make_float4(0.f, 0.f, 0.f, 0.f);
    acc[1] = make_float4(0.f, 0.f, 0.f, 0.f);
    const float4* __restrict__ W4 = (const float4*)W2;
#pragma unroll 4
    for (int k = 0; k < D1; k++) {
        float4 w = W4[k * 16 + tx];
#pragma unroll
        for (int i = 0; i < 2; i++) {
            float xv = xs[(ty * 2 + i) * D1 + k];
            acc[i].x += xv * w.x; acc[i].y += xv * w.y;
            acc[i].z += xv * w.z; acc[i].w += xv * w.w;
        }
    }
#pragma unroll
    for (int i = 0; i < 2; i++) {
        int node = nodeBase + ty * 2 + i;
        if (node < NN) ((float4*)g_h2)[node * 16 + tx] = acc[i];
    }
}

// ---------------- attention score dots ----------------

// warp per node: ssrc1/sdst1 per head
__global__ void k_score1(const float* __restrict__ as1, const float* __restrict__ ad1) {
    int n = (blockIdx.x * blockDim.x + threadIdx.x) >> 5;
    int lane = threadIdx.x & 31;
    if (n >= NN) return;
    const float4* row = (const float4*)g_h1 + n * 64;
    float4 v0 = row[lane * 2], v1 = row[lane * 2 + 1];
    float4 a0 = ((const float4*)as1)[lane * 2], a1 = ((const float4*)as1)[lane * 2 + 1];
    float4 d0 = ((const float4*)ad1)[lane * 2], d1 = ((const float4*)ad1)[lane * 2 + 1];
    float ps = v0.x * a0.x + v0.y * a0.y + v0.z * a0.z + v0.w * a0.w
             + v1.x * a1.x + v1.y * a1.y + v1.z * a1.z + v1.w * a1.w;
    float pd = v0.x * d0.x + v0.y * d0.y + v0.z * d0.z + v0.w * d0.w
             + v1.x * d1.x + v1.y * d1.y + v1.z * d1.z + v1.w * d1.w;
#pragma unroll
    for (int off = 4; off; off >>= 1) {
        ps += __shfl_xor_sync(0xffffffffu, ps, off);
        pd += __shfl_xor_sync(0xffffffffu, pd, off);
    }
    if ((lane & 7) == 0) {
        int h = lane >> 3;
        g_ssrc1[n * 4 + h] = ps;
        g_sdst1[n * 4 + h] = pd;
    }
}

// warp per node: ssrc2/sdst2 (single head)
__global__ void k_score2(const float* __restrict__ as2, const float* __restrict__ ad2) {
    int n = (blockIdx.x * blockDim.x + threadIdx.x) >> 5;
    int lane = threadIdx.x & 31;
    if (n >= NN) return;
    float2 v = ((const float2*)(g_h2 + n * 64))[lane];
    float2 a = ((const float2*)as2)[lane];
    float2 d = ((const float2*)ad2)[lane];
    float ps = v.x * a.x + v.y * a.y;
    float pd = v.x * d.x + v.y * d.y;
#pragma unroll
    for (int off = 16; off; off >>= 1) {
        ps += __shfl_xor_sync(0xffffffffu, ps, off);
        pd += __shfl_xor_sync(0xffffffffu, pd, off);
    }
    if (lane == 0) { g_ssrc2[n] = ps; g_sdst2[n] = pd; }
}

// ---------------- fused softmax + aggregation ----------------

// warp per dst node, layer1 (4 heads, 256 feature cols)
__global__ void __launch_bounds__(256) k_agg1(const float* __restrict__ ea,
                                              const float* __restrict__ b1) {
    int n = (blockIdx.x * blockDim.x + threadIdx.x) >> 5;
    int lane = threadIdx.x & 31;
    if (n >= NN) return;
    int o0 = g_off[n], deg = g_off[n + 1] - o0;
    float4 ep = *((const float4*)g_eproj);
    float4 sd = ((const float4*)g_sdst1)[n];

    // pass A: alpha (leaky relu), per-head max
    float4 mx = make_float4(-1e30f, -1e30f, -1e30f, -1e30f);
    for (int i = lane; i < deg; i += 32) {
        int p = o0 + i;
        int e = g_eid[p];
        int s = g_srcs[p];
        float a = (e < NE) ? ea[e] : g_loop[n];
        float4 ss = ((const float4*)g_ssrc1)[s];
        float4 al;
        al.x = ss.x + sd.x + a * ep.x;
        al.y = ss.y + sd.y + a * ep.y;
        al.z = ss.z + sd.z + a * ep.z;
        al.w = ss.w + sd.w + a * ep.w;
        al.x = al.x > 0.f ? al.x : 0.2f * al.x;
        al.y = al.y > 0.f ? al.y : 0.2f * al.y;
        al.z = al.z > 0.f ? al.z : 0.2f * al.z;
        al.w = al.w > 0.f ? al.w : 0.2f * al.w;
        g_alpha1[p] = al;
        mx.x = fmaxf(mx.x, al.x); mx.y = fmaxf(mx.y, al.y);
        mx.z = fmaxf(mx.z, al.z); mx.w = fmaxf(mx.w, al.w);
    }
#pragma unroll
    for (int off = 16; off; off >>= 1) {
        mx.x = fmaxf(mx.x, __shfl_xor_sync(0xffffffffu, mx.x, off));
        mx.y = fmaxf(mx.y, __shfl_xor_sync(0xffffffffu, mx.y, off));
        mx.z = fmaxf(mx.z, __shfl_xor_sync(0xffffffffu, mx.z, off));
        mx.w = fmaxf(mx.w, __shfl_xor_sync(0xffffffffu, mx.w, off));
    }
    __syncwarp();

    // pass B: exp + sum
    float4 se = make_float4(0.f, 0.f, 0.f, 0.f);
    for (int i = lane; i < deg; i += 32) {
        int p = o0 + i;
        float4 al = g_alpha1[p];
        al.x = __expf(al.x - mx.x); al.y = __expf(al.y - mx.y);
        al.z = __expf(al.z - mx.z); al.w = __expf(al.w - mx.w);
        g_alpha1[p] = al;
        se.x += al.x; se.y += al.y; se.z += al.z; se.w += al.w;
    }
#pragma unroll
    for (int off = 16; off; off >>= 1) {
        se.x += __shfl_xor_sync(0xffffffffu, se.x, off);
        se.y += __shfl_xor_sync(0xffffffffu, se.y, off);
        se.z += __shfl_xor_sync(0xffffffffu, se.z, off);
        se.w += __shfl_xor_sync(0xffffffffu, se.w, off);
    }
    float4 wv;
    wv.x = 1.f / (se.x + 1e-16f); wv.y = 1.f / (se.y + 1e-16f);
    wv.z = 1.f / (se.z + 1e-16f); wv.w = 1.f / (se.w + 1e-16f);
    __syncwarp();

    // pass C: coalesced feature gather-accumulate; lane covers cols [lane*8, lane*8+8)
    int h = lane >> 3;
    float wsel = (h == 0) ? wv.x : (h == 1) ? wv.y : (h == 2) ? wv.z : wv.w;
    float4 acc0 = make_float4(0.f, 0.f, 0.f, 0.f);
    float4 acc1 = make_float4(0.f, 0.f, 0.f, 0.f);
    for (int i = 0; i < deg; i++) {
        int p = o0 + i;
        float4 al = g_alpha1[p];
        float aw = ((h == 0) ? al.x : (h == 1) ? al.y : (h == 2) ? al.z : al.w) * wsel;
        int s = g_srcs[p];
        const float4* row = (const float4*)g_h1 + s * 64;
        float4 v0 = row[lane * 2], v1 = row[lane * 2 + 1];
        acc0.x += aw * v0.x; acc0.y += aw * v0.y; acc0.z += aw * v0.z; acc0.w += aw * v0.w;
        acc1.x += aw * v1.x; acc1.y += aw * v1.y; acc1.z += aw * v1.z; acc1.w += aw * v1.w;
    }
    float4 bb0 = ((const float4*)b1)[lane * 2], bb1 = ((const float4*)b1)[lane * 2 + 1];
    acc0.x += bb0.x; acc0.y += bb0.y; acc0.z += bb0.z; acc0.w += bb0.w;
    acc1.x += bb1.x; acc1.y += bb1.y; acc1.z += bb1.z; acc1.w += bb1.w;
    acc0.x = acc0.x > 0.f ? acc0.x : (__expf(acc0.x) - 1.f);
    acc0.y = acc0.y > 0.f ? acc0.y : (__expf(acc0.y) - 1.f);
    acc0.z = acc0.z > 0.f ? acc0.z : (__expf(acc0.z) - 1.f);
    acc0.w = acc0.w > 0.f ? acc0.w : (__expf(acc0.w) - 1.f);
    acc1.x = acc1.x > 0.f ? acc1.x : (__expf(acc1.x) - 1.f);
    acc1.y = acc1.y > 0.f ? acc1.y : (__expf(acc1.y) - 1.f);
    acc1.z = acc1.z > 0.f ? acc1.z : (__expf(acc1.z) - 1.f);
    acc1.w = acc1.w > 0.f ? acc1.w : (__expf(acc1.w) - 1.f);
    float4* orow = (float4*)g_out1 + n * 64;
    orow[lane * 2] = acc0;
    orow[lane * 2 + 1] = acc1;
}

// warp per dst node, layer2 (1 head, 64 cols) -> final output + bias2
__global__ void __launch_bounds__(256) k_agg2(const float* __restrict__ ea,
                                              const float* __restrict__ b2,
                                              float* __restrict__ dout) {
    int n = (blockIdx.x * blockDim.x + threadIdx.x) >> 5;
    int lane = threadIdx.x & 31;
    if (n >= NN) return;
    int o0 = g_off[n], deg = g_off[n + 1] - o0;
    float ep = g_eproj[4];
    float sdn = g_sdst2[n];

    float mx = -1e30f;
    for (int i = lane; i < deg; i += 32) {
        int p = o0 + i;
        int e = g_eid[p];
        int s = g_srcs[p];
        float a = (e < NE) ? ea[e] : g_loop[n];
        float al = g_ssrc2[s] + sdn + a * ep;
        al = al > 0.f ? al : 0.2f * al;
        g_alpha2[p] = al;
        mx = fmaxf(mx, al);
    }
#pragma unroll
    for (int off = 16; off; off >>= 1) mx = fmaxf(mx, __shfl_xor_sync(0xffffffffu, mx, off));
    __syncwarp();

    float se = 0.f;
    for (int i = lane; i < deg; i += 32) {
        int p = o0 + i;
        float v = __expf(g_alpha2[p] - mx);
        g_alpha2[p] = v;
        se += v;
    }
#pragma unroll
    for (int off = 16; off; off >>= 1) se += __shfl_xor_sync(0xffffffffu, se, off);
    float w = 1.f / (se + 1e-16f);
    __syncwarp();

    float2 acc = make_float2(0.f, 0.f);
    for (int i = 0; i < deg; i++) {
        int p = o0 + i;
        float aw = g_alpha2[p] * w;
        int s = g_srcs[p];
        float2 v = ((const float2*)(g_h2 + s * 64))[lane];
        acc.x += aw * v.x;
        acc.y += aw * v.y;
    }
    float2 bb = ((const float2*)b2)[lane];
    ((float2*)(dout + n * 64))[lane] = make_float2(acc.x + bb.x, acc.y + bb.y);
}

// ---------------- launch ----------------
extern "C" void kernel_launch(void* const* d_in, const int* in_sizes, int n_in,
                              void* d_out, int out_size) {
    const float* x   = (const float*)d_in[0];
    const int*   ei  = (const int*)d_in[1];
    const float* ea  = (const float*)d_in[2];
    const float* W1  = (const float*)d_in[3];
    const float* We1 = (const float*)d_in[4];
    const float* as1 = (const float*)d_in[5];
    const float* ad1 = (const float*)d_in[6];
    const float* ae1 = (const float*)d_in[7];
    const float* b1  = (const float*)d_in[8];
    const float* W2  = (const float*)d_in[9];
    const float* We2 = (const float*)d_in[10];
    const float* as2 = (const float*)d_in[11];
    const float* ad2 = (const float*)d_in[12];
    const float* ae2 = (const float*)d_in[13];
    const float* b2  = (const float*)d_in[14];
    float* dout = (float*)d_out;

    const int* src = ei;
    const int* dst = ei + NE;

    const int WPB = 8;                         // warps (nodes) per 256-thread block
    const int NB  = (NN + WPB - 1) / WPB;      // 6250

    k_zero<<<(NN + 255) / 256, 256>>>();
    k_hist<<<(NE + 255) / 256, 256>>>(dst);
    k_scan<<<1, 1024>>>();
    k_fill<<<(ET + 255) / 256, 256>>>(src, dst);
    k_loopw<<<NB, 256>>>(ea);
    k_eproj<<<1, 256>>>(We1, ae1, We2, ae2);

    k_gemm1<<<(NN + 31) / 32, 256>>>(x, W1);
    k_score1<<<NB, 256>>>(as1, ad1);
    k_agg1<<<NB, 256>>>(ea, b1);

    k_gemm2<<<(NN + 31) / 32, 256>>>(W2);
    k_score2<<<NB, 256>>>(as2, ad2);
    k_agg2<<<NB, 256>>>(ea, b2, dout);
}